// round 16
// baseline (speedup 1.0000x reference)
#include <cuda_runtime.h>
#include <cuda_bf16.h>
#include <cstdint>
#include <math.h>

#define BB 8
#define CH 256
#define CL 128
#define RR 64
#define HW 4096
#define MM 2048
#define SPLITK 16     // ATT affinity (K=4096 -> Kchunk 256)
#define SPLITK2 8     // S2 (K=2048 -> Kchunk 256)
#define SLABR 448     // slab rows per batch: [Y2(64) | Y(128) | x(256)]
#define Y2OFF 0
#define YOFF  64
#define XOFF  192
#define KT2   384     // T2 fused K  ([Y;x])
#define KZP   192     // ZP fused K  ([Y2;Y])
#define PGR   384     // stacked conv rows: PH(128)|GX(128)|G2(64)|P2(64)

// ---------------- scratch (static device globals; no runtime alloc) ----------------
__device__ __align__(16) __nv_bfloat16 g_slab[BB*SLABR*HW];   // Y2 | Y | x
__device__ __align__(16) __nv_bfloat16 g_x0b [BB*CL*HW];
__device__ __align__(16) __nv_bfloat16 g_THb [BB*CL*HW];
__device__ __align__(16) __nv_bfloat16 g_pgx [BB*PGR*HW];     // PH|GX|G2|P2
__device__ __align__(16) __nv_bfloat16 g_T2b [BB*RR*HW];
__device__ __align__(16) __nv_bfloat16 g_ZPb [BB*CH*HW];
__device__ __align__(16) __nv_bfloat16 g_ATTb[BB*CL*CL];
__device__ __align__(16) __nv_bfloat16 g_S2b [BB*CL*CL];
__device__ __align__(16) __nv_bfloat16 g_ATTP[BB*SPLITK*CL*CL];   // bf16 split-K partials
__device__ __align__(16) __nv_bfloat16 g_S2P [BB*SPLITK2*CL*CL];
__device__ __align__(16) __nv_bfloat16 g_ctwb[CL*CH];
__device__ __align__(16) __nv_bfloat16 g_pgxw[PGR*CL];        // cpw|cgw|pgw|ppw
__device__ __align__(16) __nv_bfloat16 g_wt2b[RR*KT2];        // [ptw*s1*cWw | ptw]
__device__ __align__(16) __nv_bfloat16 g_zpwb[CH*KZP];        // [s2*pWw | s1*cWw]
__device__ float g_pgxbias[PGR];
__device__ float g_biast[RR];
__device__ float g_bias2[CH];
__device__ float g_pm[BB*CH];
__device__ float g_px[BB*CH];
__device__ float g_ca[BB*CH];
__device__ float g_sam[BB*HW];
__device__ float g_sax[BB*HW];
__device__ float g_sas[BB*HW];

// ---------------- merged converts (x4 vectorized) + setup (one launch) ----------------
#define CVA (BB*CH*HW/4)
#define CVT (CVA + BB*CL*HW/4)
#define SEG0 (CVT+32768)    // ctwb
#define SEG1 (SEG0+49152)   // pgxw
#define SEG2 (SEG1+384)     // pgxbias
#define SEG3 (SEG2+49152)   // zpwb
#define SEG4 (SEG3+16384)   // wt2b copy half
#define SEG5 (SEG4+8192)    // wt2b inner-product half
#define SEG6 (SEG5+64)      // biast
#define SEG7 (SEG6+256)     // bias2
__global__ void prep_all_kernel(
    const float* __restrict__ x, const float* __restrict__ x0,
    const float* __restrict__ ctw, const float* __restrict__ cpw,
    const float* __restrict__ cgw, const float* __restrict__ pgw,
    const float* __restrict__ ppw, const float* __restrict__ cpb,
    const float* __restrict__ cgb, const float* __restrict__ pgb,
    const float* __restrict__ ppb, const float* __restrict__ pWw,
    const float* __restrict__ cWw, const float* __restrict__ ptw,
    const float* __restrict__ ptb, const float* __restrict__ cbg,
    const float* __restrict__ cbb, const float* __restrict__ cbm,
    const float* __restrict__ cbv, const float* __restrict__ cWb,
    const float* __restrict__ pbg, const float* __restrict__ pbb,
    const float* __restrict__ pbm, const float* __restrict__ pbv,
    const float* __restrict__ pWb)
{
    int i = blockIdx.x * 256 + threadIdx.x;
    auto s1f = [&](int c) { return cbg[c] * rsqrtf(cbv[c] + 1e-5f); };
    auto b1f = [&](int c) { float s = s1f(c); return cWb[c] * s + cbb[c] - cbm[c] * s; };
    auto s2f = [&](int c) { return pbg[c] * rsqrtf(pbv[c] + 1e-5f); };
    auto b2f = [&](int c) { float s = s2f(c); return pWb[c] * s + pbb[c] - pbm[c] * s; };
    if (i < CVA) {
        long e = 4L * i;
        int b = (int)(e / (CH * HW));
        long inner = e - (long)b * (CH * HW);
        float4 v = *reinterpret_cast<const float4*>(x + e);
        __nv_bfloat162 h0, h1;
        h0.x = __float2bfloat16(v.x); h0.y = __float2bfloat16(v.y);
        h1.x = __float2bfloat16(v.z); h1.y = __float2bfloat16(v.w);
        uint2 u;
        u.x = *reinterpret_cast<uint32_t*>(&h0);
        u.y = *reinterpret_cast<uint32_t*>(&h1);
        *reinterpret_cast<uint2*>(g_slab + (long)b * SLABR * HW + (long)XOFF * HW + inner) = u;
    } else if (i < CVT) {
        long e = 4L * (i - CVA);
        float4 v = *reinterpret_cast<const float4*>(x0 + e);
        __nv_bfloat162 h0, h1;
        h0.x = __float2bfloat16(v.x); h0.y = __float2bfloat16(v.y);
        h1.x = __float2bfloat16(v.z); h1.y = __float2bfloat16(v.w);
        uint2 u;
        u.x = *reinterpret_cast<uint32_t*>(&h0);
        u.y = *reinterpret_cast<uint32_t*>(&h1);
        *reinterpret_cast<uint2*>(g_x0b + e) = u;
    } else if (i < SEG0) {
        int j = i - CVT;
        g_ctwb[j] = __float2bfloat16(ctw[j]);
    } else if (i < SEG1) {
        int j = i - SEG0, r = j >> 7, k = j & 127;
        float v = (r < 128) ? cpw[r * 128 + k]
                : (r < 256) ? cgw[(r - 128) * 128 + k]
                : (r < 320) ? pgw[(r - 256) * 128 + k]
                            : ppw[(r - 320) * 128 + k];
        g_pgxw[j] = __float2bfloat16(v);
    } else if (i < SEG2) {
        int r = i - SEG1;
        g_pgxbias[r] = (r < 128) ? cpb[r] : (r < 256) ? cgb[r - 128]
                     : (r < 320) ? pgb[r - 256] : ppb[r - 320];
    } else if (i < SEG3) {
        int j = i - SEG2, o = j / KZP, k = j - o * KZP;
        float v = (k < RR) ? s2f(o) * pWw[o * RR + k]
                           : s1f(o) * cWw[o * CL + (k - RR)];
        g_zpwb[j] = __float2bfloat16(v);
    } else if (i < SEG4) {
        int j = i - SEG3, o = j >> 8, kk = j & 255;
        g_wt2b[o * KT2 + CL + kk] = __float2bfloat16(ptw[o * CH + kk]);
    } else if (i < SEG5) {
        int j = i - SEG4, o = j >> 7, m = j & 127;
        float s = 0.f;
        for (int c = 0; c < CH; c++)
            s += ptw[o * CH + c] * s1f(c) * cWw[c * CL + m];
        g_wt2b[o * KT2 + m] = __float2bfloat16(s);
    } else if (i < SEG6) {
        int o = i - SEG5;
        float bt = ptb[o];
        for (int c = 0; c < CH; c++) bt += ptw[o * CH + c] * b1f(c);
        g_biast[o] = bt;
    } else if (i < SEG7) {
        int c = i - SEG6;
        g_bias2[c] = b1f(c) + b2f(c);
    }
}

// ---------------- runtime-task BF16 tensor-core GEMM (hoisted addressing) ----------------
#define MMA_BF16(d, a0,a1,a2,a3, b0,b1) \
    asm volatile("mma.sync.aligned.m16n8k16.row.col.f32.bf16.bf16.f32 " \
        "{%0,%1,%2,%3},{%4,%5,%6,%7},{%8,%9},{%0,%1,%2,%3};" \
        : "+f"(d[0]),"+f"(d[1]),"+f"(d[2]),"+f"(d[3]) \
        : "r"(a0),"r"(a1),"r"(a2),"r"(a3),"r"(b0),"r"(b1))

#define LDSM4(r0,r1,r2,r3, ad) \
    asm volatile("ldmatrix.sync.aligned.m8n8.x4.shared.b16 {%0,%1,%2,%3},[%4];" \
        : "=r"(r0),"=r"(r1),"=r"(r2),"=r"(r3) : "r"(ad))
#define LDSM4T(r0,r1,r2,r3, ad) \
    asm volatile("ldmatrix.sync.aligned.m8n8.x4.trans.shared.b16 {%0,%1,%2,%3},[%4];" \
        : "=r"(r0),"=r"(r1),"=r"(r2),"=r"(r3) : "r"(ad))

#define CP16(s, g)  asm volatile("cp.async.cg.shared.global [%0],[%1],16;\n" :: "r"(s), "l"(g))
#define CP16Z(s, g) asm volatile("cp.async.cg.shared.global [%0],[%1],16,0;\n" :: "r"(s), "l"(g))
#define CPCOMMIT()  asm volatile("cp.async.commit_group;\n")
#define CPWAIT1()   asm volatile("cp.async.wait_group 1;\n")

struct GTask {
    const __nv_bfloat16 *A, *B;
    __nv_bfloat16* CB;        // bf16 out (all modes)
    const float *R, *bias;
    int M, K, lda, ldb, ldc;
    long sA, sB, sC;
    float alpha;
    int splitK;
    int mode;   // 0: alpha*AB+bias; 2: alpha*AB (split-K partial at z-slice); 3: AB+bias+R
};

template<bool TB>
__global__ __launch_bounds__(256, 2) void gemm_rt(GTask t0, GTask t1, int ySplit, int zSplit)
{
    const bool second = ((int)blockIdx.y >= ySplit) || ((int)blockIdx.z >= zSplit);
    const GTask& t = second ? t1 : t0;
    int by = blockIdx.y - (((int)blockIdx.y >= ySplit) ? ySplit : 0);
    int bz = blockIdx.z - (((int)blockIdx.z >= zSplit) ? zSplit : 0);

    const int batch = bz / t.splitK;
    const int kslice = bz - batch * t.splitK;
    const int Kchunk = t.K / t.splitK;
    const int k0base = kslice * Kchunk;

    const __nv_bfloat16* A = t.A + (long)batch * t.sA;
    const __nv_bfloat16* Bm = t.B + (long)batch * t.sB;
    __nv_bfloat16* CB = t.CB;
    const float* R = t.R;
    if (t.mode == 2) CB += (long)bz * t.sC;
    else {
        CB += (long)batch * t.sC;
        if (R) R += (long)batch * t.sC;
    }
    const int lda = t.lda, ldb = t.ldb, ldc = t.ldc, M = t.M;

    const int m0 = by * 128;
    const int n0 = blockIdx.x * 128;
    const int tid = threadIdx.x;
    const int warp = tid >> 5, lane = tid & 31;
    const int wm = warp >> 2, wn = warp & 3;
    const int g = lane >> 2, c = lane & 3;
    const int mi = lane >> 3, lr = lane & 7;
    const int m0w = wm * 64, n0w = wn * 32;

    __shared__ uint32_t SA[3][2048];
    __shared__ uint32_t SB[3][2048];
    const uint32_t stA = (uint32_t)__cvta_generic_to_shared(&SA[0][0]);
    const uint32_t stB = (uint32_t)__cvta_generic_to_shared(&SB[0][0]);

    float acc[4][4][4];
    #pragma unroll
    for (int i = 0; i < 4; i++)
        #pragma unroll
        for (int j = 0; j < 4; j++)
            #pragma unroll
            for (int e = 0; e < 4; e++) acc[i][j][e] = 0.f;

    const int nk = Kchunk / 32;

    // ---- hoisted cp.async addressing ----
    uint32_t saoff[2], sboff[2];
    const __nv_bfloat16 *gA[2], *gB[2];
    bool okA[2];
    const int bstep = TB ? 32 : 32 * ldb;
    #pragma unroll
    for (int it = 0; it < 2; it++) {
        int f = tid + it * 256;
        {   int row = f >> 2, cn = f & 3;
            saoff[it] = (uint32_t)(row * 4 + (cn ^ ((row >> 1) & 3))) * 16u;
            okA[it] = (m0 + row) < M;
            gA[it] = A + (okA[it] ? (long)(m0 + row) * lda : 0L) + k0base + cn * 8;
        }
        if (!TB) {
            int k = f >> 4, cn = f & 15;
            sboff[it] = (uint32_t)(k * 16 + (cn ^ (k & 7))) * 16u;
            gB[it] = Bm + (long)(k0base + k) * ldb + n0 + cn * 8;
        } else {
            int row = f >> 2, cn = f & 3;
            sboff[it] = (uint32_t)(row * 4 + (cn ^ ((row >> 1) & 3))) * 16u;
            gB[it] = Bm + (long)(n0 + row) * ldb + k0base + cn * 8;
        }
    }
    // ---- hoisted fragment offsets ----
    uint32_t aoff[2][4], boff[2][2];
    #pragma unroll
    for (int s = 0; s < 2; s++) {
        #pragma unroll
        for (int i = 0; i < 4; i++) {
            int row = m0w + 16 * i + (mi & 1) * 8 + lr;
            int chunk = 2 * s + (mi >> 1);
            aoff[s][i] = (uint32_t)(row * 4 + (chunk ^ ((row >> 1) & 3))) * 16u;
        }
        #pragma unroll
        for (int p = 0; p < 2; p++) {
            if (!TB) {
                int krow = 16 * s + (mi & 1) * 8 + lr;
                int chunk = wn * 4 + 2 * p + (mi >> 1);
                boff[s][p] = (uint32_t)(krow * 16 + (chunk ^ (krow & 7))) * 16u;
            } else {
                int nrow = n0w + 16 * p + 8 * (mi >> 1) + lr;
                int chunk = 2 * s + (mi & 1);
                boff[s][p] = (uint32_t)(nrow * 4 + (chunk ^ ((nrow >> 1) & 3))) * 16u;
            }
        }
    }

    auto issue = [&](uint32_t bA, uint32_t bB) {
        #pragma unroll
        for (int it = 0; it < 2; it++) {
            if (okA[it]) { CP16(bA + saoff[it], gA[it]); } else { CP16Z(bA + saoff[it], gA[it]); }
            CP16(bB + sboff[it], gB[it]);
            gA[it] += 32;
            gB[it] += bstep;
        }
    };

    if (0 < nk) issue(stA, stB);
    CPCOMMIT();
    if (1 < nk) issue(stA + 8192, stB + 8192);
    CPCOMMIT();

    uint32_t iA = stA + 16384, iB = stB + 16384;
    uint32_t cA = stA, cB = stB;

    for (int tt = 0; tt < nk; tt++) {
        CPWAIT1();
        __syncthreads();
        if (tt + 2 < nk) issue(iA, iB);
        CPCOMMIT();
        iA += 8192; if (iA == stA + 24576) iA = stA;
        iB += 8192; if (iB == stB + 24576) iB = stB;

        #pragma unroll
        for (int s = 0; s < 2; s++) {
            uint32_t bfr[4][2];
            #pragma unroll
            for (int p = 0; p < 2; p++) {
                if (!TB) {
                    LDSM4T(bfr[2*p][0], bfr[2*p][1], bfr[2*p+1][0], bfr[2*p+1][1], cB + boff[s][p]);
                } else {
                    LDSM4(bfr[2*p][0], bfr[2*p][1], bfr[2*p+1][0], bfr[2*p+1][1], cB + boff[s][p]);
                }
            }
            #pragma unroll
            for (int i = 0; i < 4; i++) {
                uint32_t a0, a1, a2, a3;
                LDSM4(a0, a1, a2, a3, cA + aoff[s][i]);
                #pragma unroll
                for (int j = 0; j < 4; j++)
                    MMA_BF16(acc[i][j], a0, a1, a2, a3, bfr[j][0], bfr[j][1]);
            }
        }
        cA += 8192; if (cA == stA + 24576) cA = stA;
        cB += 8192; if (cB == stB + 24576) cB = stB;
    }

    // ---- epilogue ----
    #pragma unroll
    for (int i = 0; i < 4; i++) {
        int gm0 = m0 + m0w + i * 16 + g;
        #pragma unroll
        for (int half = 0; half < 2; half++) {
            int gm = gm0 + half * 8;
            if (gm >= M) continue;
            float bv = (t.mode != 2 && t.bias) ? t.bias[gm] : 0.f;
            #pragma unroll
            for (int j = 0; j < 4; j++) {
                int gn = n0 + n0w + j * 8 + 2 * c;
                long idx = (long)gm * ldc + gn;
                float v0 = acc[i][j][half * 2 + 0];
                float v1 = acc[i][j][half * 2 + 1];
                float o0, o1;
                if (t.mode == 2)      { o0 = t.alpha * v0;            o1 = t.alpha * v1; }
                else if (t.mode == 3) { o0 = v0 + bv + R[idx];        o1 = v1 + bv + R[idx + 1]; }
                else                  { o0 = t.alpha * v0 + bv;       o1 = t.alpha * v1 + bv; }
                __nv_bfloat162 h;
                h.x = __float2bfloat16(o0); h.y = __float2bfloat16(o1);
                *reinterpret_cast<__nv_bfloat162*>(&CB[idx]) = h;
            }
        }
    }
}

static inline GTask mkTask(const __nv_bfloat16* A, const __nv_bfloat16* B,
                           __nv_bfloat16* CB, const float* R, const float* bias,
                           int M, int K, int lda, int ldb, int ldc,
                           long sA, long sB, long sC, float alpha, int splitK, int mode) {
    GTask t; t.A = A; t.B = B; t.CB = CB; t.R = R; t.bias = bias;
    t.M = M; t.K = K; t.lda = lda; t.ldb = ldb; t.ldc = ldc;
    t.sA = sA; t.sB = sB; t.sC = sC; t.alpha = alpha; t.splitK = splitK; t.mode = mode;
    return t;
}

// ---------------- merged deterministic split-K reduce (bf16 partials, x2 vector) ----------------
__global__ void reduce_both() {
    int i = blockIdx.x * 256 + threadIdx.x;   // pair index
    const int PERP = CL * CL / 2;             // 8192 pairs per matrix
    if (i < BB * PERP) {
        int b = i / PERP, r = i - b * PERP;
        const __nv_bfloat162* src = reinterpret_cast<const __nv_bfloat162*>(g_ATTP);
        float s0 = 0.f, s1 = 0.f;
        #pragma unroll
        for (int k = 0; k < SPLITK; k++) {
            __nv_bfloat162 h = src[((long)b * SPLITK + k) * PERP + r];
            s0 += __bfloat162float(h.x);
            s1 += __bfloat162float(h.y);
        }
        __nv_bfloat162 o;
        o.x = __float2bfloat16(s0); o.y = __float2bfloat16(s1);
        reinterpret_cast<__nv_bfloat162*>(g_ATTb)[i] = o;
    } else {
        int j = i - BB * PERP;
        int b = j / PERP, r = j - b * PERP;
        const __nv_bfloat162* src = reinterpret_cast<const __nv_bfloat162*>(g_S2P);
        float s0 = 0.f, s1 = 0.f;
        #pragma unroll
        for (int k = 0; k < SPLITK2; k++) {
            __nv_bfloat162 h = src[((long)b * SPLITK2 + k) * PERP + r];
            s0 += __bfloat162float(h.x);
            s1 += __bfloat162float(h.y);
        }
        __nv_bfloat162 o;
        o.x = __float2bfloat16(s0); o.y = __float2bfloat16(s1);
        reinterpret_cast<__nv_bfloat162*>(g_S2b)[j] = o;
    }
}

// ---------------- CBAM: channel pooling (mean+max over HW, bf16 in) ----------------
__global__ void chanpool_kernel() {
    int c = blockIdx.x, b = blockIdx.y;
    int t = threadIdx.x;
    const __nv_bfloat162* p = reinterpret_cast<const __nv_bfloat162*>(
        g_ZPb + ((long)b * CH + c) * HW);
    float s = 0.f, mx = -1e30f;
    for (int i = t; i < HW / 2; i += 256) {
        __nv_bfloat162 h = p[i];
        float v0 = __bfloat162float(h.x), v1 = __bfloat162float(h.y);
        s += v0 + v1;
        mx = fmaxf(mx, fmaxf(v0, v1));
    }
    __shared__ float ss[256];
    __shared__ float sm[256];
    ss[t] = s; sm[t] = mx;
    __syncthreads();
    for (int o = 128; o > 0; o >>= 1) {
        if (t < o) { ss[t] += ss[t + o]; sm[t] = fmaxf(sm[t], sm[t + o]); }
        __syncthreads();
    }
    if (t == 0) {
        g_pm[b * CH + c] = ss[0] * (1.f / HW);
        g_px[b * CH + c] = sm[0];
    }
}

// ---------------- CBAM: channel-attention MLP ----------------
__global__ void camlp_kernel(const float* __restrict__ fc1, const float* __restrict__ fc2) {
    int b = blockIdx.x;
    int t = threadIdx.x;
    __shared__ float hm[16], hx[16];
    if (t < 16) {
        float s = 0.f;
        for (int c = 0; c < CH; c++) s += fc1[t * CH + c] * g_pm[b * CH + c];
        hm[t] = fmaxf(s, 0.f);
    } else if (t < 32) {
        int h = t - 16;
        float s = 0.f;
        for (int c = 0; c < CH; c++) s += fc1[h * CH + c] * g_px[b * CH + c];
        hx[h] = fmaxf(s, 0.f);
    }
    __syncthreads();
    float sm = 0.f, sx = 0.f;
    #pragma unroll
    for (int h = 0; h < 16; h++) {
        float w = fc2[t * 16 + h];
        sm += w * hm[h];
        sx += w * hx[h];
    }
    g_ca[b * CH + t] = 1.f / (1.f + expf(-(sm + sx)));
}

// ---------------- CBAM: spatial pooling over channels of z_pnl*ca ----------------
__global__ void spool_kernel() {
    __shared__ float cas[CH];
    int idx = blockIdx.x * 256 + threadIdx.x;
    int b = idx / HW;
    int p = idx - b * HW;
    for (int c = threadIdx.x; c < CH; c += 256) cas[c] = g_ca[b * CH + c];
    __syncthreads();
    float s = 0.f, mx = -1e30f;
    for (int c = 0; c < CH; c++) {
        float v = __bfloat162float(g_ZPb[((long)b * CH + c) * HW + p]) * cas[c];
        s += v;
        mx = fmaxf(mx, v);
    }
    g_sam[idx] = s * (1.f / CH);
    g_sax[idx] = mx;
}

// ---------------- CBAM: 7x7 spatial conv + sigmoid ----------------
__global__ void sconv_kernel(const float* __restrict__ w) {
    int idx = blockIdx.x * 256 + threadIdx.x;
    int b = idx / HW;
    int p = idx - b * HW;
    int h = p >> 6, wq = p & 63;
    float s = 0.f;
    #pragma unroll
    for (int kh = 0; kh < 7; kh++) {
        int ih = h + kh - 3;
        if (ih < 0 || ih >= 64) continue;
        #pragma unroll
        for (int kw = 0; kw < 7; kw++) {
            int iw = wq + kw - 3;
            if (iw < 0 || iw >= 64) continue;
            int q = (ih << 6) | iw;
            s += w[kh * 7 + kw] * g_sam[b * HW + q] + w[49 + kh * 7 + kw] * g_sax[b * HW + q];
        }
    }
    g_sas[idx] = 1.f / (1.f + expf(-s));
}

// ---------------- final weighted fusion (x4 vectorized) ----------------
__global__ void final_kernel(const float* __restrict__ x, const float* __restrict__ fwp,
                             float* __restrict__ out) {
    long e = 4L * (blockIdx.x * 256 + threadIdx.x);
    long p = e % HW;
    long bc = e / HW;
    long b = bc / CH;
    float fw = *fwp;
    uint2 zr = *reinterpret_cast<const uint2*>(g_ZPb + e);
    __nv_bfloat162 z0 = *reinterpret_cast<__nv_bfloat162*>(&zr.x);
    __nv_bfloat162 z1 = *reinterpret_cast<__nv_bfloat162*>(&zr.y);
    float4 xv = *reinterpret_cast<const float4*>(x + e);
    float ca = g_ca[bc];
    const float* sas = g_sas + b * HW + p;
    float4 o;
    o.x = fw * __bfloat162float(z0.x) * ca * sas[0] + (1.f - fw) * xv.x;
    o.y = fw * __bfloat162float(z0.y) * ca * sas[1] + (1.f - fw) * xv.y;
    o.z = fw * __bfloat162float(z1.x) * ca * sas[2] + (1.f - fw) * xv.z;
    o.w = fw * __bfloat162float(z1.y) * ca * sas[3] + (1.f - fw) * xv.w;
    *reinterpret_cast<float4*>(out + e) = o;
}

// ---------------- launch ----------------
extern "C" void kernel_launch(void* const* d_in, const int* in_sizes, int n_in,
                              void* d_out, int out_size) {
    const float* x   = (const float*)d_in[0];
    const float* x0  = (const float*)d_in[1];
    const float* cgw = (const float*)d_in[2];
    const float* cgb = (const float*)d_in[3];
    const float* ctw = (const float*)d_in[4];
    const float* ctb = (const float*)d_in[5];
    const float* cpw = (const float*)d_in[6];
    const float* cpb = (const float*)d_in[7];
    const float* cWw = (const float*)d_in[8];
    const float* cWb = (const float*)d_in[9];
    const float* cbg = (const float*)d_in[10];
    const float* cbb = (const float*)d_in[11];
    const float* cbm = (const float*)d_in[12];
    const float* cbv = (const float*)d_in[13];
    const float* pgw = (const float*)d_in[14];
    const float* pgb = (const float*)d_in[15];
    const float* ptw = (const float*)d_in[16];
    const float* ptb = (const float*)d_in[17];
    const float* ppw = (const float*)d_in[18];
    const float* ppb = (const float*)d_in[19];
    const float* pWw = (const float*)d_in[20];
    const float* pWb = (const float*)d_in[21];
    const float* pbg = (const float*)d_in[22];
    const float* pbb = (const float*)d_in[23];
    const float* pbm = (const float*)d_in[24];
    const float* pbv = (const float*)d_in[25];
    const float* fc1 = (const float*)d_in[26];
    const float* fc2 = (const float*)d_in[27];
    const float* saw = (const float*)d_in[28];
    const float* fwp = (const float*)d_in[29];
    float* out = (float*)d_out;

    __nv_bfloat16 *SLAB, *X0B, *THB, *PGX, *T2B, *ZPB, *ATTB, *S2B, *ATTP, *S2P;
    __nv_bfloat16 *CTWB, *PGXW, *WT2B, *ZPWB;
    float *PGXBI, *BIAST, *BIAS2;
    cudaGetSymbolAddress((void**)&SLAB, g_slab);
    cudaGetSymbolAddress((void**)&X0B,  g_x0b);
    cudaGetSymbolAddress((void**)&THB,  g_THb);
    cudaGetSymbolAddress((void**)&PGX,  g_pgx);
    cudaGetSymbolAddress((void**)&T2B,  g_T2b);
    cudaGetSymbolAddress((void**)&ZPB,  g_ZPb);
    cudaGetSymbolAddress((void**)&ATTB, g_ATTb);
    cudaGetSymbolAddress((void**)&S2B,  g_S2b);
    cudaGetSymbolAddress((void**)&ATTP, g_ATTP);
    cudaGetSymbolAddress((void**)&S2P,  g_S2P);
    cudaGetSymbolAddress((void**)&CTWB, g_ctwb);
    cudaGetSymbolAddress((void**)&PGXW, g_pgxw);
    cudaGetSymbolAddress((void**)&WT2B, g_wt2b);
    cudaGetSymbolAddress((void**)&ZPWB, g_zpwb);
    cudaGetSymbolAddress((void**)&PGXBI,g_pgxbias);
    cudaGetSymbolAddress((void**)&BIAST,g_biast);
    cudaGetSymbolAddress((void**)&BIAS2,g_bias2);

    const long sSLAB = (long)SLABR * HW;
    const long sPGX  = (long)PGR * HW;
    const int BIG = 1 << 30;

    // 1) merged converts + weight prep
    prep_all_kernel<<<(SEG7 + 255) / 256, 256>>>(
        x, x0, ctw, cpw, cgw, pgw, ppw, cpb, cgb, pgb, ppb, pWw, cWw, ptw, ptb,
        cbg, cbb, cbm, cbv, cWb, pbg, pbb, pbm, pbv, pWb);

    // 2) stacked conv PH|GX|G2|P2 (y 0-2) + TH (y 3)
    {
        GTask t0 = mkTask(PGXW, X0B, PGX, nullptr, PGXBI,
                          PGR, CL, CL, HW, HW, 0L, (long)CL*HW, sPGX, 1.f, 1, 0);
        GTask t1 = mkTask(CTWB, SLAB + (long)XOFF*HW, THB, nullptr, ctb,
                          CL, CH, CH, HW, HW, 0L, sSLAB, (long)CL*HW, 1.f, 1, 0);
        gemm_rt<false><<<dim3(HW/128, 4, BB), 256>>>(t0, t1, 3, BIG);
    }
    // 3) dual split-K: ATT (z<128) + S2 (z>=128), bf16 partials
    {
        GTask t0 = mkTask(THB, PGX, ATTP, nullptr, nullptr,
                          CL, HW, HW, HW, CL, (long)CL*HW, sPGX, (long)CL*CL,
                          1.f/CL, SPLITK, 2);
        GTask t1 = mkTask(PGX + (long)256*HW, PGX + (long)320*HW, S2P, nullptr, nullptr,
                          CL, MM, MM, MM, CL, sPGX, sPGX, (long)CL*CL,
                          1.f/MM, SPLITK2, 2);
        gemm_rt<true><<<dim3(1, 1, BB*SPLITK + BB*SPLITK2), 256>>>(t0, t1, BIG, BB*SPLITK);
    }
    // 4) merged reduce -> ATTB, S2B  (x2 vectorized, 512 CTAs)
    reduce_both<<<2*BB*(CL*CL/2)/256, 256>>>();
    // 5) Y = ATT @ GX  -> slab rows YOFF..
    {
        GTask t0 = mkTask(ATTB, PGX + (long)CL*HW, SLAB + (long)YOFF*HW, nullptr, nullptr,
                          CL, CL, CL, HW, HW, (long)CL*CL, sPGX, sSLAB, 1.f, 1, 0);
        gemm_rt<false><<<dim3(HW/128, 1, BB), 256>>>(t0, t0, BIG, BIG);
    }
    // 6) T2 fused over [Y; x] (K=384)
    {
        GTask t0 = mkTask(WT2B, SLAB + (long)YOFF*HW, T2B, nullptr, BIAST,
                          RR, KT2, KT2, HW, HW, 0L, sSLAB, (long)RR*HW, 1.f, 1, 0);
        gemm_rt<false><<<dim3(HW/128, 1, BB), 256>>>(t0, t0, BIG, BIG);
    }
    // 7) Y2v = S2 @ T2v -> slab rows 0-63
    {
        GTask t0 = mkTask(S2B, T2B, SLAB + (long)Y2OFF*HW, nullptr, nullptr,
                          CL, CL, CL, MM, MM, (long)CL*CL, (long)RR*HW, sSLAB, 1.f, 1, 0);
        gemm_rt<false><<<dim3(MM/128, 1, BB), 256>>>(t0, t0, BIG, BIG);
    }
    // 8) ZP = [s2*pWw | s1*cWw] @ [Y2;Y] + (b1+b2) + x  (fp32 residual, mode 3)
    {
        GTask t0 = mkTask(ZPWB, SLAB, ZPB, x, BIAS2,
                          CH, KZP, KZP, HW, HW, 0L, sSLAB, (long)CH*HW, 1.f, 1, 3);
        gemm_rt<false><<<dim3(HW/128, CH/128, BB), 256>>>(t0, t0, BIG, BIG);
    }

    // ---- CBAM + fusion ----
    chanpool_kernel<<<dim3(CH, BB), 256>>>();
    camlp_kernel<<<BB, 256>>>(fc1, fc2);
    spool_kernel<<<BB*HW/256, 256>>>();
    sconv_kernel<<<BB*HW/256, 256>>>(saw);
    final_kernel<<<BB*CH*HW/1024, 256>>>(x, fwp, out);
}

// round 17
// speedup vs baseline: 1.0733x; 1.0733x over previous
#include <cuda_runtime.h>
#include <cuda_bf16.h>
#include <cstdint>
#include <math.h>

#define BB 8
#define CH 256
#define CL 128
#define RR 64
#define HW 4096
#define MM 2048
#define SPLITK 16     // ATT affinity (K=4096 -> Kchunk 256)
#define SPLITK2 8     // S2 (K=2048 -> Kchunk 256)
#define SLABR 448     // slab rows per batch: [Y2(64) | Y(128) | x(256)]
#define Y2OFF 0
#define YOFF  64
#define XOFF  192
#define KT2   384     // T2 fused K  ([Y;x])
#define KZP   192     // ZP fused K  ([Y2;Y])
#define PGR   384     // stacked conv rows: PH(128)|GX(128)|G2(64)|P2(64)

// ---------------- scratch (static device globals; no runtime alloc) ----------------
__device__ __align__(16) __nv_bfloat16 g_slab[BB*SLABR*HW];   // Y2 | Y | x
__device__ __align__(16) __nv_bfloat16 g_x0b [BB*CL*HW];
__device__ __align__(16) __nv_bfloat16 g_THb [BB*CL*HW];
__device__ __align__(16) __nv_bfloat16 g_pgx [BB*PGR*HW];     // PH|GX|G2|P2
__device__ __align__(16) __nv_bfloat16 g_T2b [BB*RR*HW];
__device__ __align__(16) __nv_bfloat16 g_ZPb [BB*CH*HW];
__device__ __align__(16) __nv_bfloat16 g_ATTb[BB*CL*CL];
__device__ __align__(16) __nv_bfloat16 g_S2b [BB*CL*CL];
__device__ __align__(16) __nv_bfloat16 g_ATTP[BB*SPLITK*CL*CL];   // bf16 split-K partials
__device__ __align__(16) __nv_bfloat16 g_S2P [BB*SPLITK2*CL*CL];
__device__ __align__(16) __nv_bfloat16 g_ctwb[CL*CH];
__device__ __align__(16) __nv_bfloat16 g_pgxw[PGR*CL];        // cpw|cgw|pgw|ppw
__device__ __align__(16) __nv_bfloat16 g_wt2b[RR*KT2];        // [ptw*s1*cWw | ptw]
__device__ __align__(16) __nv_bfloat16 g_zpwb[CH*KZP];        // [s2*pWw | s1*cWw]
__device__ float g_pgxbias[PGR];
__device__ float g_biast[RR];
__device__ float g_bias2[CH];
__device__ float g_pm[BB*CH];
__device__ float g_px[BB*CH];
__device__ float g_ca[BB*CH];
__device__ float g_sam[BB*HW];
__device__ float g_sax[BB*HW];
__device__ float g_sas[BB*HW];

// ---------------- merged converts (x4 vectorized) + setup (one launch) ----------------
#define CVA (BB*CH*HW/4)
#define CVT (CVA + BB*CL*HW/4)
#define SEG0 (CVT+32768)    // ctwb
#define SEG1 (SEG0+49152)   // pgxw
#define SEG2 (SEG1+384)     // pgxbias
#define SEG3 (SEG2+49152)   // zpwb
#define SEG4 (SEG3+16384)   // wt2b copy half
#define SEG5 (SEG4+8192)    // wt2b inner-product half
#define SEG6 (SEG5+64)      // biast
#define SEG7 (SEG6+256)     // bias2
__global__ void prep_all_kernel(
    const float* __restrict__ x, const float* __restrict__ x0,
    const float* __restrict__ ctw, const float* __restrict__ cpw,
    const float* __restrict__ cgw, const float* __restrict__ pgw,
    const float* __restrict__ ppw, const float* __restrict__ cpb,
    const float* __restrict__ cgb, const float* __restrict__ pgb,
    const float* __restrict__ ppb, const float* __restrict__ pWw,
    const float* __restrict__ cWw, const float* __restrict__ ptw,
    const float* __restrict__ ptb, const float* __restrict__ cbg,
    const float* __restrict__ cbb, const float* __restrict__ cbm,
    const float* __restrict__ cbv, const float* __restrict__ cWb,
    const float* __restrict__ pbg, const float* __restrict__ pbb,
    const float* __restrict__ pbm, const float* __restrict__ pbv,
    const float* __restrict__ pWb)
{
    int i = blockIdx.x * 256 + threadIdx.x;
    auto s1f = [&](int c) { return cbg[c] * rsqrtf(cbv[c] + 1e-5f); };
    auto b1f = [&](int c) { float s = s1f(c); return cWb[c] * s + cbb[c] - cbm[c] * s; };
    auto s2f = [&](int c) { return pbg[c] * rsqrtf(pbv[c] + 1e-5f); };
    auto b2f = [&](int c) { float s = s2f(c); return pWb[c] * s + pbb[c] - pbm[c] * s; };
    if (i < CVA) {
        long e = 4L * i;
        int b = (int)(e / (CH * HW));
        long inner = e - (long)b * (CH * HW);
        float4 v = *reinterpret_cast<const float4*>(x + e);
        __nv_bfloat162 h0, h1;
        h0.x = __float2bfloat16(v.x); h0.y = __float2bfloat16(v.y);
        h1.x = __float2bfloat16(v.z); h1.y = __float2bfloat16(v.w);
        uint2 u;
        u.x = *reinterpret_cast<uint32_t*>(&h0);
        u.y = *reinterpret_cast<uint32_t*>(&h1);
        *reinterpret_cast<uint2*>(g_slab + (long)b * SLABR * HW + (long)XOFF * HW + inner) = u;
    } else if (i < CVT) {
        long e = 4L * (i - CVA);
        float4 v = *reinterpret_cast<const float4*>(x0 + e);
        __nv_bfloat162 h0, h1;
        h0.x = __float2bfloat16(v.x); h0.y = __float2bfloat16(v.y);
        h1.x = __float2bfloat16(v.z); h1.y = __float2bfloat16(v.w);
        uint2 u;
        u.x = *reinterpret_cast<uint32_t*>(&h0);
        u.y = *reinterpret_cast<uint32_t*>(&h1);
        *reinterpret_cast<uint2*>(g_x0b + e) = u;
    } else if (i < SEG0) {
        int j = i - CVT;
        g_ctwb[j] = __float2bfloat16(ctw[j]);
    } else if (i < SEG1) {
        int j = i - SEG0, r = j >> 7, k = j & 127;
        float v = (r < 128) ? cpw[r * 128 + k]
                : (r < 256) ? cgw[(r - 128) * 128 + k]
                : (r < 320) ? pgw[(r - 256) * 128 + k]
                            : ppw[(r - 320) * 128 + k];
        g_pgxw[j] = __float2bfloat16(v);
    } else if (i < SEG2) {
        int r = i - SEG1;
        g_pgxbias[r] = (r < 128) ? cpb[r] : (r < 256) ? cgb[r - 128]
                     : (r < 320) ? pgb[r - 256] : ppb[r - 320];
    } else if (i < SEG3) {
        int j = i - SEG2, o = j / KZP, k = j - o * KZP;
        float v = (k < RR) ? s2f(o) * pWw[o * RR + k]
                           : s1f(o) * cWw[o * CL + (k - RR)];
        g_zpwb[j] = __float2bfloat16(v);
    } else if (i < SEG4) {
        int j = i - SEG3, o = j >> 8, kk = j & 255;
        g_wt2b[o * KT2 + CL + kk] = __float2bfloat16(ptw[o * CH + kk]);
    } else if (i < SEG5) {
        int j = i - SEG4, o = j >> 7, m = j & 127;
        float s = 0.f;
        for (int c = 0; c < CH; c++)
            s += ptw[o * CH + c] * s1f(c) * cWw[c * CL + m];
        g_wt2b[o * KT2 + m] = __float2bfloat16(s);
    } else if (i < SEG6) {
        int o = i - SEG5;
        float bt = ptb[o];
        for (int c = 0; c < CH; c++) bt += ptw[o * CH + c] * b1f(c);
        g_biast[o] = bt;
    } else if (i < SEG7) {
        int c = i - SEG6;
        g_bias2[c] = b1f(c) + b2f(c);
    }
}

// ---------------- runtime-task BF16 tensor-core GEMM (compile-time MODE) ----------------
#define MMA_BF16(d, a0,a1,a2,a3, b0,b1) \
    asm volatile("mma.sync.aligned.m16n8k16.row.col.f32.bf16.bf16.f32 " \
        "{%0,%1,%2,%3},{%4,%5,%6,%7},{%8,%9},{%0,%1,%2,%3};" \
        : "+f"(d[0]),"+f"(d[1]),"+f"(d[2]),"+f"(d[3]) \
        : "r"(a0),"r"(a1),"r"(a2),"r"(a3),"r"(b0),"r"(b1))

#define LDSM4(r0,r1,r2,r3, ad) \
    asm volatile("ldmatrix.sync.aligned.m8n8.x4.shared.b16 {%0,%1,%2,%3},[%4];" \
        : "=r"(r0),"=r"(r1),"=r"(r2),"=r"(r3) : "r"(ad))
#define LDSM4T(r0,r1,r2,r3, ad) \
    asm volatile("ldmatrix.sync.aligned.m8n8.x4.trans.shared.b16 {%0,%1,%2,%3},[%4];" \
        : "=r"(r0),"=r"(r1),"=r"(r2),"=r"(r3) : "r"(ad))

#define CP16(s, g)  asm volatile("cp.async.cg.shared.global [%0],[%1],16;\n" :: "r"(s), "l"(g))
#define CP16Z(s, g) asm volatile("cp.async.cg.shared.global [%0],[%1],16,0;\n" :: "r"(s), "l"(g))
#define CPCOMMIT()  asm volatile("cp.async.commit_group;\n")
#define CPWAIT1()   asm volatile("cp.async.wait_group 1;\n")

struct GTask {
    const __nv_bfloat16 *A, *B;
    __nv_bfloat16* CB;          // bf16 out (all modes)
    const __nv_bfloat16* Rb;    // mode 4 residual (bf16)
    const float *R, *bias;      // mode 3 residual (fp32)
    int M, K, lda, ldb, ldc;
    long sA, sB, sC, sR;
    float alpha;
    int splitK;
};

// MODE: 0: alpha*AB+bias; 2: alpha*AB (split-K partial at z-slice);
//       3: AB+bias+R(fp32); 4: AB+bias+Rb(bf16)
template<bool TB, int MODE>
__global__ __launch_bounds__(256, 2) void gemm_rt(GTask t0, GTask t1, int ySplit, int zSplit)
{
    const bool second = ((int)blockIdx.y >= ySplit) || ((int)blockIdx.z >= zSplit);
    const GTask& t = second ? t1 : t0;
    int by = blockIdx.y - (((int)blockIdx.y >= ySplit) ? ySplit : 0);
    int bz = blockIdx.z - (((int)blockIdx.z >= zSplit) ? zSplit : 0);

    const int batch = bz / t.splitK;
    const int kslice = bz - batch * t.splitK;
    const int Kchunk = t.K / t.splitK;
    const int k0base = kslice * Kchunk;

    const __nv_bfloat16* A = t.A + (long)batch * t.sA;
    const __nv_bfloat16* Bm = t.B + (long)batch * t.sB;
    __nv_bfloat16* CB = t.CB;
    const float* R = t.R;
    const __nv_bfloat16* Rb = t.Rb;
    if (MODE == 2) CB += (long)bz * t.sC;
    else {
        CB += (long)batch * t.sC;
        if (MODE == 3) R += (long)batch * t.sC;
        if (MODE == 4) Rb += (long)batch * t.sR;
    }
    const int lda = t.lda, ldb = t.ldb, ldc = t.ldc, M = t.M;

    const int m0 = by * 128;
    const int n0 = blockIdx.x * 128;
    const int tid = threadIdx.x;
    const int warp = tid >> 5, lane = tid & 31;
    const int wm = warp >> 2, wn = warp & 3;
    const int g = lane >> 2, c = lane & 3;
    const int mi = lane >> 3, lr = lane & 7;
    const int m0w = wm * 64, n0w = wn * 32;

    __shared__ uint32_t SA[3][2048];
    __shared__ uint32_t SB[3][2048];
    const uint32_t stA = (uint32_t)__cvta_generic_to_shared(&SA[0][0]);
    const uint32_t stB = (uint32_t)__cvta_generic_to_shared(&SB[0][0]);

    float acc[4][4][4];
    #pragma unroll
    for (int i = 0; i < 4; i++)
        #pragma unroll
        for (int j = 0; j < 4; j++)
            #pragma unroll
            for (int e = 0; e < 4; e++) acc[i][j][e] = 0.f;

    const int nk = Kchunk / 32;

    // ---- hoisted cp.async addressing ----
    uint32_t saoff[2], sboff[2];
    const __nv_bfloat16 *gA[2], *gB[2];
    bool okA[2];
    const int bstep = TB ? 32 : 32 * ldb;
    #pragma unroll
    for (int it = 0; it < 2; it++) {
        int f = tid + it * 256;
        {   int row = f >> 2, cn = f & 3;
            saoff[it] = (uint32_t)(row * 4 + (cn ^ ((row >> 1) & 3))) * 16u;
            okA[it] = (m0 + row) < M;
            gA[it] = A + (okA[it] ? (long)(m0 + row) * lda : 0L) + k0base + cn * 8;
        }
        if (!TB) {
            int k = f >> 4, cn = f & 15;
            sboff[it] = (uint32_t)(k * 16 + (cn ^ (k & 7))) * 16u;
            gB[it] = Bm + (long)(k0base + k) * ldb + n0 + cn * 8;
        } else {
            int row = f >> 2, cn = f & 3;
            sboff[it] = (uint32_t)(row * 4 + (cn ^ ((row >> 1) & 3))) * 16u;
            gB[it] = Bm + (long)(n0 + row) * ldb + k0base + cn * 8;
        }
    }
    // ---- hoisted fragment offsets ----
    uint32_t aoff[2][4], boff[2][2];
    #pragma unroll
    for (int s = 0; s < 2; s++) {
        #pragma unroll
        for (int i = 0; i < 4; i++) {
            int row = m0w + 16 * i + (mi & 1) * 8 + lr;
            int chunk = 2 * s + (mi >> 1);
            aoff[s][i] = (uint32_t)(row * 4 + (chunk ^ ((row >> 1) & 3))) * 16u;
        }
        #pragma unroll
        for (int p = 0; p < 2; p++) {
            if (!TB) {
                int krow = 16 * s + (mi & 1) * 8 + lr;
                int chunk = wn * 4 + 2 * p + (mi >> 1);
                boff[s][p] = (uint32_t)(krow * 16 + (chunk ^ (krow & 7))) * 16u;
            } else {
                int nrow = n0w + 16 * p + 8 * (mi >> 1) + lr;
                int chunk = 2 * s + (mi & 1);
                boff[s][p] = (uint32_t)(nrow * 4 + (chunk ^ ((nrow >> 1) & 3))) * 16u;
            }
        }
    }

    auto issue = [&](uint32_t bA, uint32_t bB) {
        #pragma unroll
        for (int it = 0; it < 2; it++) {
            if (okA[it]) { CP16(bA + saoff[it], gA[it]); } else { CP16Z(bA + saoff[it], gA[it]); }
            CP16(bB + sboff[it], gB[it]);
            gA[it] += 32;
            gB[it] += bstep;
        }
    };

    if (0 < nk) issue(stA, stB);
    CPCOMMIT();
    if (1 < nk) issue(stA + 8192, stB + 8192);
    CPCOMMIT();

    uint32_t iA = stA + 16384, iB = stB + 16384;
    uint32_t cA = stA, cB = stB;

    for (int tt = 0; tt < nk; tt++) {
        CPWAIT1();
        __syncthreads();
        if (tt + 2 < nk) issue(iA, iB);
        CPCOMMIT();
        iA += 8192; if (iA == stA + 24576) iA = stA;
        iB += 8192; if (iB == stB + 24576) iB = stB;

        #pragma unroll
        for (int s = 0; s < 2; s++) {
            uint32_t bfr[4][2];
            #pragma unroll
            for (int p = 0; p < 2; p++) {
                if (!TB) {
                    LDSM4T(bfr[2*p][0], bfr[2*p][1], bfr[2*p+1][0], bfr[2*p+1][1], cB + boff[s][p]);
                } else {
                    LDSM4(bfr[2*p][0], bfr[2*p][1], bfr[2*p+1][0], bfr[2*p+1][1], cB + boff[s][p]);
                }
            }
            #pragma unroll
            for (int i = 0; i < 4; i++) {
                uint32_t a0, a1, a2, a3;
                LDSM4(a0, a1, a2, a3, cA + aoff[s][i]);
                #pragma unroll
                for (int j = 0; j < 4; j++)
                    MMA_BF16(acc[i][j], a0, a1, a2, a3, bfr[j][0], bfr[j][1]);
            }
        }
        cA += 8192; if (cA == stA + 24576) cA = stA;
        cB += 8192; if (cB == stB + 24576) cB = stB;
    }

    // ---- epilogue (compile-time MODE) ----
    #pragma unroll
    for (int i = 0; i < 4; i++) {
        int gm0 = m0 + m0w + i * 16 + g;
        #pragma unroll
        for (int half = 0; half < 2; half++) {
            int gm = gm0 + half * 8;
            if (gm >= M) continue;
            float bv = (MODE != 2 && t.bias) ? t.bias[gm] : 0.f;
            #pragma unroll
            for (int j = 0; j < 4; j++) {
                int gn = n0 + n0w + j * 8 + 2 * c;
                long idx = (long)gm * ldc + gn;
                float v0 = acc[i][j][half * 2 + 0];
                float v1 = acc[i][j][half * 2 + 1];
                float o0, o1;
                if (MODE == 2)      { o0 = t.alpha * v0;            o1 = t.alpha * v1; }
                else if (MODE == 3) { o0 = v0 + bv + R[idx];        o1 = v1 + bv + R[idx + 1]; }
                else if (MODE == 4) {
                    __nv_bfloat162 r = *reinterpret_cast<const __nv_bfloat162*>(&Rb[idx]);
                    o0 = v0 + bv + __bfloat162float(r.x);
                    o1 = v1 + bv + __bfloat162float(r.y);
                }
                else                { o0 = t.alpha * v0 + bv;       o1 = t.alpha * v1 + bv; }
                __nv_bfloat162 h;
                h.x = __float2bfloat16(o0); h.y = __float2bfloat16(o1);
                *reinterpret_cast<__nv_bfloat162*>(&CB[idx]) = h;
            }
        }
    }
}

static inline GTask mkTask(const __nv_bfloat16* A, const __nv_bfloat16* B,
                           __nv_bfloat16* CB, const float* R, const float* bias,
                           int M, int K, int lda, int ldb, int ldc,
                           long sA, long sB, long sC, float alpha, int splitK,
                           const __nv_bfloat16* Rb = nullptr, long sR = 0) {
    GTask t; t.A = A; t.B = B; t.CB = CB; t.Rb = Rb; t.R = R; t.bias = bias;
    t.M = M; t.K = K; t.lda = lda; t.ldb = ldb; t.ldc = ldc;
    t.sA = sA; t.sB = sB; t.sC = sC; t.sR = sR;
    t.alpha = alpha; t.splitK = splitK;
    return t;
}

// ---------------- merged deterministic split-K reduce (bf16 partials, x2 vector) ----------------
__global__ void reduce_both() {
    int i = blockIdx.x * 256 + threadIdx.x;   // pair index
    const int PERP = CL * CL / 2;             // 8192 pairs per matrix
    if (i < BB * PERP) {
        int b = i / PERP, r = i - b * PERP;
        const __nv_bfloat162* src = reinterpret_cast<const __nv_bfloat162*>(g_ATTP);
        float s0 = 0.f, s1 = 0.f;
        #pragma unroll
        for (int k = 0; k < SPLITK; k++) {
            __nv_bfloat162 h = src[((long)b * SPLITK + k) * PERP + r];
            s0 += __bfloat162float(h.x);
            s1 += __bfloat162float(h.y);
        }
        __nv_bfloat162 o;
        o.x = __float2bfloat16(s0); o.y = __float2bfloat16(s1);
        reinterpret_cast<__nv_bfloat162*>(g_ATTb)[i] = o;
    } else {
        int j = i - BB * PERP;
        int b = j / PERP, r = j - b * PERP;
        const __nv_bfloat162* src = reinterpret_cast<const __nv_bfloat162*>(g_S2P);
        float s0 = 0.f, s1 = 0.f;
        #pragma unroll
        for (int k = 0; k < SPLITK2; k++) {
            __nv_bfloat162 h = src[((long)b * SPLITK2 + k) * PERP + r];
            s0 += __bfloat162float(h.x);
            s1 += __bfloat162float(h.y);
        }
        __nv_bfloat162 o;
        o.x = __float2bfloat16(s0); o.y = __float2bfloat16(s1);
        reinterpret_cast<__nv_bfloat162*>(g_S2b)[j] = o;
    }
}

// ---------------- CBAM: channel pooling (mean+max over HW, bf16 in) ----------------
__global__ void chanpool_kernel() {
    int c = blockIdx.x, b = blockIdx.y;
    int t = threadIdx.x;
    const __nv_bfloat162* p = reinterpret_cast<const __nv_bfloat162*>(
        g_ZPb + ((long)b * CH + c) * HW);
    float s = 0.f, mx = -1e30f;
    for (int i = t; i < HW / 2; i += 256) {
        __nv_bfloat162 h = p[i];
        float v0 = __bfloat162float(h.x), v1 = __bfloat162float(h.y);
        s += v0 + v1;
        mx = fmaxf(mx, fmaxf(v0, v1));
    }
    __shared__ float ss[256];
    __shared__ float sm[256];
    ss[t] = s; sm[t] = mx;
    __syncthreads();
    for (int o = 128; o > 0; o >>= 1) {
        if (t < o) { ss[t] += ss[t + o]; sm[t] = fmaxf(sm[t], sm[t + o]); }
        __syncthreads();
    }
    if (t == 0) {
        g_pm[b * CH + c] = ss[0] * (1.f / HW);
        g_px[b * CH + c] = sm[0];
    }
}

// ---------------- CBAM: channel-attention MLP ----------------
__global__ void camlp_kernel(const float* __restrict__ fc1, const float* __restrict__ fc2) {
    int b = blockIdx.x;
    int t = threadIdx.x;
    __shared__ float hm[16], hx[16];
    if (t < 16) {
        float s = 0.f;
        for (int c = 0; c < CH; c++) s += fc1[t * CH + c] * g_pm[b * CH + c];
        hm[t] = fmaxf(s, 0.f);
    } else if (t < 32) {
        int h = t - 16;
        float s = 0.f;
        for (int c = 0; c < CH; c++) s += fc1[h * CH + c] * g_px[b * CH + c];
        hx[h] = fmaxf(s, 0.f);
    }
    __syncthreads();
    float sm = 0.f, sx = 0.f;
    #pragma unroll
    for (int h = 0; h < 16; h++) {
        float w = fc2[t * 16 + h];
        sm += w * hm[h];
        sx += w * hx[h];
    }
    g_ca[b * CH + t] = 1.f / (1.f + expf(-(sm + sx)));
}

// ---------------- CBAM: spatial pooling over channels of z_pnl*ca ----------------
__global__ void spool_kernel() {
    __shared__ float cas[CH];
    int idx = blockIdx.x * 256 + threadIdx.x;
    int b = idx / HW;
    int p = idx - b * HW;
    for (int c = threadIdx.x; c < CH; c += 256) cas[c] = g_ca[b * CH + c];
    __syncthreads();
    float s = 0.f, mx = -1e30f;
    for (int c = 0; c < CH; c++) {
        float v = __bfloat162float(g_ZPb[((long)b * CH + c) * HW + p]) * cas[c];
        s += v;
        mx = fmaxf(mx, v);
    }
    g_sam[idx] = s * (1.f / CH);
    g_sax[idx] = mx;
}

// ---------------- CBAM: 7x7 spatial conv + sigmoid ----------------
__global__ void sconv_kernel(const float* __restrict__ w) {
    int idx = blockIdx.x * 256 + threadIdx.x;
    int b = idx / HW;
    int p = idx - b * HW;
    int h = p >> 6, wq = p & 63;
    float s = 0.f;
    #pragma unroll
    for (int kh = 0; kh < 7; kh++) {
        int ih = h + kh - 3;
        if (ih < 0 || ih >= 64) continue;
        #pragma unroll
        for (int kw = 0; kw < 7; kw++) {
            int iw = wq + kw - 3;
            if (iw < 0 || iw >= 64) continue;
            int q = (ih << 6) | iw;
            s += w[kh * 7 + kw] * g_sam[b * HW + q] + w[49 + kh * 7 + kw] * g_sax[b * HW + q];
        }
    }
    g_sas[idx] = 1.f / (1.f + expf(-s));
}

// ---------------- final weighted fusion (x4 vectorized, exact fp32 x) ----------------
__global__ void final_kernel(const float* __restrict__ x, const float* __restrict__ fwp,
                             float* __restrict__ out) {
    long e = 4L * (blockIdx.x * 256 + threadIdx.x);
    long p = e % HW;
    long bc = e / HW;
    long b = bc / CH;
    float fw = *fwp;
    uint2 zr = *reinterpret_cast<const uint2*>(g_ZPb + e);
    __nv_bfloat162 z0 = *reinterpret_cast<__nv_bfloat162*>(&zr.x);
    __nv_bfloat162 z1 = *reinterpret_cast<__nv_bfloat162*>(&zr.y);
    float4 xv = *reinterpret_cast<const float4*>(x + e);
    float ca = g_ca[bc];
    const float* sas = g_sas + b * HW + p;
    float4 o;
    o.x = fw * __bfloat162float(z0.x) * ca * sas[0] + (1.f - fw) * xv.x;
    o.y = fw * __bfloat162float(z0.y) * ca * sas[1] + (1.f - fw) * xv.y;
    o.z = fw * __bfloat162float(z1.x) * ca * sas[2] + (1.f - fw) * xv.z;
    o.w = fw * __bfloat162float(z1.y) * ca * sas[3] + (1.f - fw) * xv.w;
    *reinterpret_cast<float4*>(out + e) = o;
}

// ---------------- launch ----------------
extern "C" void kernel_launch(void* const* d_in, const int* in_sizes, int n_in,
                              void* d_out, int out_size) {
    const float* x   = (const float*)d_in[0];
    const float* x0  = (const float*)d_in[1];
    const float* cgw = (const float*)d_in[2];
    const float* cgb = (const float*)d_in[3];
    const float* ctw = (const float*)d_in[4];
    const float* ctb = (const float*)d_in[5];
    const float* cpw = (const float*)d_in[6];
    const float* cpb = (const float*)d_in[7];
    const float* cWw = (const float*)d_in[8];
    const float* cWb = (const float*)d_in[9];
    const float* cbg = (const float*)d_in[10];
    const float* cbb = (const float*)d_in[11];
    const float* cbm = (const float*)d_in[12];
    const float* cbv = (const float*)d_in[13];
    const float* pgw = (const float*)d_in[14];
    const float* pgb = (const float*)d_in[15];
    const float* ptw = (const float*)d_in[16];
    const float* ptb = (const float*)d_in[17];
    const float* ppw = (const float*)d_in[18];
    const float* ppb = (const float*)d_in[19];
    const float* pWw = (const float*)d_in[20];
    const float* pWb = (const float*)d_in[21];
    const float* pbg = (const float*)d_in[22];
    const float* pbb = (const float*)d_in[23];
    const float* pbm = (const float*)d_in[24];
    const float* pbv = (const float*)d_in[25];
    const float* fc1 = (const float*)d_in[26];
    const float* fc2 = (const float*)d_in[27];
    const float* saw = (const float*)d_in[28];
    const float* fwp = (const float*)d_in[29];
    float* out = (float*)d_out;

    __nv_bfloat16 *SLAB, *X0B, *THB, *PGX, *T2B, *ZPB, *ATTB, *S2B, *ATTP, *S2P;
    __nv_bfloat16 *CTWB, *PGXW, *WT2B, *ZPWB;
    float *PGXBI, *BIAST, *BIAS2;
    cudaGetSymbolAddress((void**)&SLAB, g_slab);
    cudaGetSymbolAddress((void**)&X0B,  g_x0b);
    cudaGetSymbolAddress((void**)&THB,  g_THb);
    cudaGetSymbolAddress((void**)&PGX,  g_pgx);
    cudaGetSymbolAddress((void**)&T2B,  g_T2b);
    cudaGetSymbolAddress((void**)&ZPB,  g_ZPb);
    cudaGetSymbolAddress((void**)&ATTB, g_ATTb);
    cudaGetSymbolAddress((void**)&S2B,  g_S2b);
    cudaGetSymbolAddress((void**)&ATTP, g_ATTP);
    cudaGetSymbolAddress((void**)&S2P,  g_S2P);
    cudaGetSymbolAddress((void**)&CTWB, g_ctwb);
    cudaGetSymbolAddress((void**)&PGXW, g_pgxw);
    cudaGetSymbolAddress((void**)&WT2B, g_wt2b);
    cudaGetSymbolAddress((void**)&ZPWB, g_zpwb);
    cudaGetSymbolAddress((void**)&PGXBI,g_pgxbias);
    cudaGetSymbolAddress((void**)&BIAST,g_biast);
    cudaGetSymbolAddress((void**)&BIAS2,g_bias2);

    const long sSLAB = (long)SLABR * HW;
    const long sPGX  = (long)PGR * HW;
    const int BIG = 1 << 30;

    // 1) merged converts + weight prep
    prep_all_kernel<<<(SEG7 + 255) / 256, 256>>>(
        x, x0, ctw, cpw, cgw, pgw, ppw, cpb, cgb, pgb, ppb, pWw, cWw, ptw, ptb,
        cbg, cbb, cbm, cbv, cWb, pbg, pbb, pbm, pbv, pWb);

    // 2) stacked conv PH|GX|G2|P2 (y 0-2) + TH (y 3)
    {
        GTask t0 = mkTask(PGXW, X0B, PGX, nullptr, PGXBI,
                          PGR, CL, CL, HW, HW, 0L, (long)CL*HW, sPGX, 1.f, 1);
        GTask t1 = mkTask(CTWB, SLAB + (long)XOFF*HW, THB, nullptr, ctb,
                          CL, CH, CH, HW, HW, 0L, sSLAB, (long)CL*HW, 1.f, 1);
        gemm_rt<false, 0><<<dim3(HW/128, 4, BB), 256>>>(t0, t1, 3, BIG);
    }
    // 3) dual split-K: ATT (z<128) + S2 (z>=128), bf16 partials
    {
        GTask t0 = mkTask(THB, PGX, ATTP, nullptr, nullptr,
                          CL, HW, HW, HW, CL, (long)CL*HW, sPGX, (long)CL*CL,
                          1.f/CL, SPLITK);
        GTask t1 = mkTask(PGX + (long)256*HW, PGX + (long)320*HW, S2P, nullptr, nullptr,
                          CL, MM, MM, MM, CL, sPGX, sPGX, (long)CL*CL,
                          1.f/MM, SPLITK2);
        gemm_rt<true, 2><<<dim3(1, 1, BB*SPLITK + BB*SPLITK2), 256>>>(t0, t1, BIG, BB*SPLITK);
    }
    // 4) merged reduce -> ATTB, S2B  (x2 vectorized, 512 CTAs)
    reduce_both<<<2*BB*(CL*CL/2)/256, 256>>>();
    // 5) Y = ATT @ GX  -> slab rows YOFF..
    {
        GTask t0 = mkTask(ATTB, PGX + (long)CL*HW, SLAB + (long)YOFF*HW, nullptr, nullptr,
                          CL, CL, CL, HW, HW, (long)CL*CL, sPGX, sSLAB, 1.f, 1);
        gemm_rt<false, 0><<<dim3(HW/128, 1, BB), 256>>>(t0, t0, BIG, BIG);
    }
    // 6) T2 fused over [Y; x] (K=384)
    {
        GTask t0 = mkTask(WT2B, SLAB + (long)YOFF*HW, T2B, nullptr, BIAST,
                          RR, KT2, KT2, HW, HW, 0L, sSLAB, (long)RR*HW, 1.f, 1);
        gemm_rt<false, 0><<<dim3(HW/128, 1, BB), 256>>>(t0, t0, BIG, BIG);
    }
    // 7) Y2v = S2 @ T2v -> slab rows 0-63
    {
        GTask t0 = mkTask(S2B, T2B, SLAB + (long)Y2OFF*HW, nullptr, nullptr,
                          CL, CL, CL, MM, MM, (long)CL*CL, (long)RR*HW, sSLAB, 1.f, 1);
        gemm_rt<false, 0><<<dim3(MM/128, 1, BB), 256>>>(t0, t0, BIG, BIG);
    }
    // 8) ZP = [s2*pWw | s1*cWw] @ [Y2;Y] + (b1+b2) + x(bf16 from slab)  (mode 4)
    {
        GTask t0 = mkTask(ZPWB, SLAB, ZPB, nullptr, BIAS2,
                          CH, KZP, KZP, HW, HW, 0L, sSLAB, (long)CH*HW, 1.f, 1,
                          SLAB + (long)XOFF*HW, sSLAB);
        gemm_rt<false, 4><<<dim3(HW/128, CH/128, BB), 256>>>(t0, t0, BIG, BIG);
    }

    // ---- CBAM + fusion ----
    chanpool_kernel<<<dim3(CH, BB), 256>>>();
    camlp_kernel<<<BB, 256>>>(fc1, fc2);
    spool_kernel<<<BB*HW/256, 256>>>();
    sconv_kernel<<<BB*HW/256, 256>>>(saw);
    final_kernel<<<BB*CH*HW/1024, 256>>>(x, fwp, out);
}